// round 13
// baseline (speedup 1.0000x reference)
#include <cuda_runtime.h>
#include <cuda_fp16.h>
#include <math.h>

// MoE router via mma.sync m16n8k16 fp16 2-plane split (3 f32-acc products):
//   logits = x[T,4096] @ W[64,4096]^T; x = xh+xm (exact residual),
//   W*64 = Wh+Wm (exact scale, undone at softmax).
// R13: macro-chunks of 64 k (two stride-40 sub-buffers) -> half the syncs;
// STAGES=2; write-ahead inline W split (no wsplit kernel); top2 with 4
// tokens/warp and batched loads for MLP.

#define HID  4096
#define NE   64
#define TM   128
#define KCM  64                   // macro chunk (two 32-wide sub-buffers)
#define KSPL 4
#define KPER (HID / KSPL)         // 1024
#define NCH  (KPER / KCM)         // 16
#define NT   256
#define XSTR 40                   // row stride in floats (160B), per sub-buffer
#define SUBB 20480                // x sub-buffer bytes (128*40*4)
#define XSTGB (2 * SUBB)          // 40960 per x stage
#define WOFF  (2 * XSTGB)         // 81920: W buffers after 2 x stages
#define WSUBB 8192                // W sub-buffer bytes (64*160 / 2... = 64 rows*128B? no: 64*160=10240? see below)
#undef WSUBB
#define WROWB 160                 // B row stride bytes per sub (20 uint2)
#define WSUB  (NE * WROWB)        // 10240 bytes per 32-wide W sub-buffer
#define WBUFB (2 * WSUB)          // 20480 per W macro buffer
#define SMEM_BYTES (WOFF + 2 * WBUFB)    // 122880

static __device__ float g_partial[KSPL * 8192 * NE];   // 8 MB

__device__ __forceinline__ unsigned smem_u32(const void* p) {
    unsigned r;
    asm("{ .reg .u64 t; cvta.to.shared.u64 t, %1; cvt.u32.u64 %0, t; }"
        : "=r"(r) : "l"(p));
    return r;
}
__device__ __forceinline__ void pairsplit(const float* p, unsigned& h, unsigned& m) {
    float2 v = *(const float2*)p;
    __half2 hh = __float22half2_rn(v);
    float2 hb = __half22float2(hh);
    __half2 mm = __float22half2_rn(make_float2(v.x - hb.x, v.y - hb.y));
    h = *(unsigned*)&hh;
    m = *(unsigned*)&mm;
}
__device__ __forceinline__ void valsplit(float2 v, unsigned& h, unsigned& m) {
    __half2 hh = __float22half2_rn(v);
    float2 hb = __half22float2(hh);
    __half2 mm = __float22half2_rn(make_float2(v.x - hb.x, v.y - hb.y));
    h = *(unsigned*)&hh;
    m = *(unsigned*)&mm;
}
__device__ __forceinline__ void mma_f16(float* c, const unsigned* a, const unsigned* b) {
    asm volatile(
        "mma.sync.aligned.m16n8k16.row.col.f32.f16.f16.f32 "
        "{%0,%1,%2,%3},{%4,%5,%6,%7},{%8,%9},{%0,%1,%2,%3};"
        : "+f"(c[0]), "+f"(c[1]), "+f"(c[2]), "+f"(c[3])
        : "r"(a[0]), "r"(a[1]), "r"(a[2]), "r"(a[3]), "r"(b[0]), "r"(b[1]));
}
__device__ __forceinline__ void sts128(unsigned addr, unsigned a, unsigned b,
                                       unsigned cc, unsigned d) {
    asm volatile("st.shared.v4.b32 [%0], {%1,%2,%3,%4};"
                 :: "r"(addr), "r"(a), "r"(b), "r"(cc), "r"(d));
}
#define CP16(dst, src) asm volatile("cp.async.cg.shared.global [%0],[%1],16;" :: "r"(dst), "l"(src))
#define CPCOMMIT()     asm volatile("cp.async.commit_group;")
#define CPWAIT1()      asm volatile("cp.async.wait_group 1;")

// -------- kernel 1: split-K(4) GEMM, macro-chunks, inline W split --------
__global__ __launch_bounds__(NT, 2) void moe_gemm_kernel(
    const float* __restrict__ x, const float* __restrict__ w, int T)
{
    extern __shared__ char smc[];
    const unsigned sbase = smem_u32(smc);
    const int tid = threadIdx.x;
    const int wid = tid >> 5;
    const int lane = tid & 31;
    const int tok0 = blockIdx.x * TM;
    const int ks = blockIdx.y;
    const int kbase = ks * KPER;

    // x cp.async mapping: 8 x 16B/thread per macro-chunk (2 sub-buffers)
    const float* xsrc[8]; unsigned xdst[8];
    #pragma unroll
    for (int it = 0; it < 8; it++) {
        int sub = it >> 2, itl = it & 3;
        int u = itl * NT + tid, row = u >> 3, c4 = u & 7;
        xsrc[it] = x + (size_t)(tok0 + row) * HID + kbase + sub * 32 + c4 * 4;
        xdst[it] = sbase + (unsigned)(sub * SUBB) + (unsigned)(row * XSTR + c4 * 4) * 4;
    }
    // W: 4 float4/thread per macro-chunk (LDG -> split -> STS write-ahead)
    const float4* wsrc[4]; unsigned wsts[4];
    #pragma unroll
    for (int q = 0; q < 4; q++) {
        int sub = q >> 1, ql = q & 1;
        int u = ql * NT + tid, row = u >> 3, c4 = u & 7;
        wsrc[q] = (const float4*)(w + (size_t)row * HID + kbase + sub * 32 + c4 * 4);
        wsts[q] = sbase + WOFF + (unsigned)(sub * WSUB) + (unsigned)(row * WROWB + c4 * 16);
    }

    float acc[8][4];
    #pragma unroll
    for (int nt = 0; nt < 8; nt++)
        #pragma unroll
        for (int i = 0; i < 4; i++) acc[nt][i] = 0.f;

    // prologue: W chunk 0 -> buf0; wreg = W chunk 1; x chunk 0 -> stage 0
    float4 wreg[4];
    #pragma unroll
    for (int q = 0; q < 4; q++) wreg[q] = wsrc[q][0];
    #pragma unroll
    for (int q = 0; q < 4; q++) {
        float4 v = wreg[q];
        unsigned h0, m0, h1, m1;
        valsplit(make_float2(v.x * 64.f, v.y * 64.f), h0, m0);
        valsplit(make_float2(v.z * 64.f, v.w * 64.f), h1, m1);
        sts128(wsts[q], h0, m0, h1, m1);
    }
    #pragma unroll
    for (int q = 0; q < 4; q++) wreg[q] = wsrc[q][16];
    #pragma unroll
    for (int it = 0; it < 8; it++) CP16(xdst[it], xsrc[it]);
    CPCOMMIT();

    const int eq = lane >> 2;           // groupID 0..7
    const int kq = lane & 3;            // threadInGroup 0..3
    const int rbase = wid * 16 + eq;

    #pragma unroll 1
    for (int c = 0; c < NCH; c++) {
        __syncthreads();                // compute c-1 done: stage/buf (c+1)&1 free
        if (c + 1 < NCH) {
            unsigned so = (unsigned)(((c + 1) & 1) * XSTGB);
            #pragma unroll
            for (int it = 0; it < 8; it++) CP16(xdst[it] + so, xsrc[it] + (c + 1) * KCM);
            unsigned wo = (unsigned)(((c + 1) & 1) * WBUFB);
            #pragma unroll
            for (int q = 0; q < 4; q++) {
                float4 v = wreg[q];
                unsigned h0, m0, h1, m1;
                valsplit(make_float2(v.x * 64.f, v.y * 64.f), h0, m0);
                valsplit(make_float2(v.z * 64.f, v.w * 64.f), h1, m1);
                sts128(wsts[q] + wo, h0, m0, h1, m1);
            }
            if (c + 2 < NCH) {
                #pragma unroll
                for (int q = 0; q < 4; q++) wreg[q] = wsrc[q][(c + 2) * 16];
            }
        }
        CPCOMMIT();
        CPWAIT1();                      // x macro-chunk c landed (this thread)
        __syncthreads();                // x + W buf c&1 visible to all

        const char* stg = smc + (c & 1) * XSTGB;
        const char* wbb = smc + WOFF + (c & 1) * WBUFB;

        #pragma unroll
        for (int s = 0; s < 4; s++) {          // four k16 steps per macro-chunk
            const int s2 = s >> 1, sl = s & 1;
            const int kl = sl * 16 + kq * 2;
            const float* sx = (const float*)(stg + s2 * SUBB);
            const uint2* bw = (const uint2*)(wbb + s2 * WSUB);
            unsigned Ah[4], Am[4];
            pairsplit(sx + rbase * XSTR + kl,           Ah[0], Am[0]);
            pairsplit(sx + (rbase + 8) * XSTR + kl,     Ah[1], Am[1]);
            pairsplit(sx + rbase * XSTR + kl + 8,       Ah[2], Am[2]);
            pairsplit(sx + (rbase + 8) * XSTR + kl + 8, Ah[3], Am[3]);
            unsigned Bh[8][2], Bm[8][2];
            #pragma unroll
            for (int nt = 0; nt < 8; nt++) {
                int e = nt * 8 + eq;
                uint2 t0 = bw[e * 20 + sl * 8 + kq];
                uint2 t1 = bw[e * 20 + sl * 8 + 4 + kq];
                Bh[nt][0] = t0.x; Bm[nt][0] = t0.y;
                Bh[nt][1] = t1.x; Bm[nt][1] = t1.y;
            }
            #pragma unroll
            for (int nt = 0; nt < 8; nt++) {
                mma_f16(acc[nt], Ah, Bh[nt]);
                mma_f16(acc[nt], Ah, Bm[nt]);
                mma_f16(acc[nt], Am, Bh[nt]);
            }
        }
    }

    // ---- write fp32 partials (x64-scaled; top2 unscales at softmax)
    {
        int row = tok0 + rbase;
        float* d0 = g_partial + ((size_t)ks * T + row) * NE;
        float* d8 = d0 + (size_t)8 * NE;
        #pragma unroll
        for (int nt = 0; nt < 8; nt++) {
            int col = nt * 8 + kq * 2;
            *(float2*)(d0 + col) = make_float2(acc[nt][0], acc[nt][1]);
            *(float2*)(d8 + col) = make_float2(acc[nt][2], acc[nt][3]);
        }
    }
}

// -------- kernel 2: reduce + top-2 + softmax (4 tokens/warp, high MLP) -----
__global__ __launch_bounds__(256) void moe_top2_kernel(float* __restrict__ out,
                                                       int T, int write_map) {
    const int lane = threadIdx.x & 31;
    const int warp = threadIdx.x >> 5;
    const int tbase = blockIdx.x * 32 + warp * 4;
    const int c0 = lane * 2, c1 = lane * 2 + 1;

    // batched loads: 16 independent float2 LDGs in flight
    float2 s[4];
    #pragma unroll
    for (int tok = 0; tok < 4; tok++) {
        float2 a0 = *(const float2*)(g_partial + ((size_t)0 * T + tbase + tok) * NE + c0);
        float2 a1 = *(const float2*)(g_partial + ((size_t)1 * T + tbase + tok) * NE + c0);
        float2 a2 = *(const float2*)(g_partial + ((size_t)2 * T + tbase + tok) * NE + c0);
        float2 a3 = *(const float2*)(g_partial + ((size_t)3 * T + tbase + tok) * NE + c0);
        s[tok] = make_float2((a0.x + a1.x) + (a2.x + a3.x),
                             (a0.y + a1.y) + (a2.y + a3.y));
    }

    #pragma unroll
    for (int tok = 0; tok < 4; tok++) {
        const int t = tbase + tok;
        float v1, v2; int i1, i2;
        if (s[tok].y > s[tok].x) { v1 = s[tok].y; i1 = c1; v2 = s[tok].x; i2 = c0; }
        else                     { v1 = s[tok].x; i1 = c0; v2 = s[tok].y; i2 = c1; }
        #pragma unroll
        for (int sh = 16; sh >= 1; sh >>= 1) {
            float ov1 = __shfl_xor_sync(0xffffffffu, v1, sh);
            int   oi1 = __shfl_xor_sync(0xffffffffu, i1, sh);
            float ov2 = __shfl_xor_sync(0xffffffffu, v2, sh);
            int   oi2 = __shfl_xor_sync(0xffffffffu, i2, sh);
            bool ob = (ov1 > v1) || (ov1 == v1 && oi1 < i1);   // jax tie-break
            float nv1 = ob ? ov1 : v1;  int ni1 = ob ? oi1 : i1;
            float cv  = ob ? v1  : ov1; int ci  = ob ? i1  : oi1;
            float sv  = ob ? ov2 : v2;  int si  = ob ? oi2 : i2;
            bool b2 = (cv > sv) || (cv == sv && ci < si);
            v2 = b2 ? cv : sv; i2 = b2 ? ci : si;
            v1 = nv1; i1 = ni1;
        }
        // logits carry the exact x64 W scale; undo on the difference (exact)
        float ex = expf((v2 - v1) * 0.015625f);   // <= 1, stable
        float inv = 1.f / (1.f + ex);
        float pp1 = inv, pp2 = ex * inv;

        float2 po;
        po.x = (c0 == i1) ? pp1 : ((c0 == i2) ? pp2 : 0.f);
        po.y = (c1 == i1) ? pp1 : ((c1 == i2) ? pp2 : 0.f);
        *(float2*)(out + (size_t)t * NE + c0) = po;
        if (write_map) {
            float2 mo;
            mo.x = (c0 == i1 || c0 == i2) ? 1.f : 0.f;
            mo.y = (c1 == i1 || c1 == i2) ? 1.f : 0.f;
            *(float2*)(out + (size_t)T * NE + (size_t)t * NE + c0) = mo;
        }
    }
}

extern "C" void kernel_launch(void* const* d_in, const int* in_sizes, int n_in,
                              void* d_out, int out_size) {
    const float* x = (const float*)d_in[0];   // [2048,4,4096] fp32
    const float* w = (const float*)d_in[1];   // [64,4096] fp32
    float* out = (float*)d_out;
    int T = in_sizes[0] / HID;                // 8192
    int write_map = (out_size >= 2 * T * NE) ? 1 : 0;

    static int smem_set = 0;
    if (!smem_set) {
        cudaFuncSetAttribute(moe_gemm_kernel,
                             cudaFuncAttributeMaxDynamicSharedMemorySize, SMEM_BYTES);
        smem_set = 1;
    }
    dim3 grid(T / TM, KSPL);
    moe_gemm_kernel<<<grid, NT, SMEM_BYTES>>>(x, w, T);
    moe_top2_kernel<<<T / 32, 256>>>(out, T, write_map);
}